// round 12
// baseline (speedup 1.0000x reference)
#include <cuda_runtime.h>
#include <cuda_fp16.h>
#include <math.h>

#define NN 50000
#define NE 800000
#define CH 64
#define FE 16
#define NL 13          // conv1 + 12 hidden
#define NG 500
#define NCHUNK ((NN + 15) / 16)
#define SCAN_NB ((NN + 255) / 256)
#define NSLOT 8        // spread slots for stats atomics

typedef unsigned long long ull;

// ---------------- f32x2 helpers ----------------
__device__ __forceinline__ ull pk2(float x, float y) {
    ull r;
    asm("mov.b64 %0, {%1, %2};" : "=l"(r) : "r"(__float_as_uint(x)), "r"(__float_as_uint(y)));
    return r;
}
__device__ __forceinline__ void fma2(ull& d, ull a, ull b) {
    asm("fma.rn.f32x2 %0, %1, %2, %3;" : "=l"(d) : "l"(a), "l"(b), "l"(d));
}
__device__ __forceinline__ float2 upk(ull v) {
    unsigned lo, hi;
    asm("mov.b64 {%0, %1}, %2;" : "=r"(lo), "=r"(hi) : "l"(v));
    return make_float2(__uint_as_float(lo), __uint_as_float(hi));
}

// ---------------- scratch ----------------
__device__ int2   g_se[(size_t)NL * NE];     // (src, float-bits ew) per layer, CSR order
__device__ float  g_degacc[(size_t)NL * NN]; // weighted degree accumulators
__device__ float  g_dis[(size_t)NL * NN];
__device__ int    g_rowptr[NN + 1];          // per-block-local exclusive; global = + boff[i>>8]
__device__ int    g_cursor[NN];
__device__ int4   g_cs[NE];                  // (src, eid, dst, 0) per CSR slot
__device__ int    g_bsum[SCAN_NB + 1];
__device__ int    g_boff[SCAN_NB + 1];
__device__ __half g_gbuf[(size_t)NN * CH];   // fp16 gather buffer
__device__ __half g_curh[(size_t)NN * CH];   // fp16 current features
__device__ float  g_S[(size_t)NN * CH];      // fp32 skip accumulator
__device__ double g_stats2[NL][NSLOT][2][CH];
__device__ float  g_pool[NG * CH];

// global rowptr accessor (i in [0, NN])
__device__ __forceinline__ int rp(int i) {
    if (i >= NN) return g_rowptr[NN];
    return g_rowptr[i] + g_boff[i >> 8];
}

// unpack 4 half2 (from uint4) scaled-accumulate
__device__ __forceinline__ void acc8(float* acc, float w, uint4 q) {
    float2 f0 = __half22float2(*(__half2*)&q.x);
    float2 f1 = __half22float2(*(__half2*)&q.y);
    float2 f2 = __half22float2(*(__half2*)&q.z);
    float2 f3 = __half22float2(*(__half2*)&q.w);
    acc[0] += w * f0.x; acc[1] += w * f0.y;
    acc[2] += w * f1.x; acc[3] += w * f1.y;
    acc[4] += w * f2.x; acc[5] += w * f2.y;
    acc[6] += w * f3.x; acc[7] += w * f3.y;
}

__device__ __forceinline__ uint4 pack8h(const float* v) {
    __half2 h0 = __floats2half2_rn(v[0], v[1]);
    __half2 h1 = __floats2half2_rn(v[2], v[3]);
    __half2 h2 = __floats2half2_rn(v[4], v[5]);
    __half2 h3 = __floats2half2_rn(v[6], v[7]);
    return make_uint4(*(unsigned*)&h0, *(unsigned*)&h1, *(unsigned*)&h2, *(unsigned*)&h3);
}

// ---------------- setup ----------------
__global__ void k_count(const int* __restrict__ dst) {
    int e = blockIdx.x * blockDim.x + threadIdx.x;
    if (e < NE) atomicAdd(&g_cursor[dst[e]], 1);
}

__device__ __forceinline__ int blockscan256(int v, int* warpsums) {
    int lane = threadIdx.x & 31, wid = threadIdx.x >> 5;
    int x = v;
    #pragma unroll
    for (int o = 1; o < 32; o <<= 1) {
        int t = __shfl_up_sync(0xffffffffu, x, o);
        if (lane >= o) x += t;
    }
    if (lane == 31) warpsums[wid] = x;
    __syncthreads();
    if (wid == 0 && lane < 8) {
        int w = warpsums[lane];
        #pragma unroll
        for (int o = 1; o < 8; o <<= 1) {
            int t = __shfl_up_sync(0xffu, w, o);
            if (lane >= o) w += t;
        }
        warpsums[lane] = w;
    }
    __syncthreads();
    return x + (wid > 0 ? warpsums[wid - 1] : 0);
}

__global__ void k_scanA() {
    __shared__ int ws[8];
    int i = blockIdx.x * 256 + threadIdx.x;
    int v = (i < NN) ? g_cursor[i] : 0;
    int incl = blockscan256(v, ws);
    if (i < NN) {
        g_rowptr[i] = incl - v;
        g_cursor[i] = incl - v;
    }
    if (threadIdx.x == 255) g_bsum[blockIdx.x] = incl;
}

__global__ void k_scanB() {
    __shared__ int ws[8];
    int t = threadIdx.x;
    int v = (t < SCAN_NB) ? g_bsum[t] : 0;
    int incl = blockscan256(v, ws);
    if (t < SCAN_NB) g_boff[t] = incl - v;
    if (t == 255) g_rowptr[NN] = incl;
}

__global__ void k_fill(const int* __restrict__ src, const int* __restrict__ dst) {
    int e = blockIdx.x * blockDim.x + threadIdx.x;
    if (e < NE) {
        int d = dst[e];
        int pos = atomicAdd(&g_cursor[d], 1) + g_boff[d >> 8];
        g_cs[pos] = make_int4(src[e], e, d, 0);
    }
}

// ---------------- all-layers edge MLP: writes (src, ew) pairs + degree atomics ----------------
__global__ void __launch_bounds__(256) k_mlp(
    const float* __restrict__ ea,
    const float* __restrict__ m1W1, const float* __restrict__ m1b1,
    const float* __restrict__ m2W1, const float* __restrict__ m2b1,
    const float* __restrict__ hm1W, const float* __restrict__ hm1b,
    const float* __restrict__ hm2W, const float* __restrict__ hm2b)
{
    __shared__ float sW1[NL][FE][FE];
    __shared__ float sb1[NL][FE];
    __shared__ float sW2[NL][FE];
    __shared__ float sb2[NL];
    int tid = threadIdx.x;
    for (int t = tid; t < NL * FE * FE; t += blockDim.x) {
        int j = t / (FE * FE), r = t % (FE * FE);
        sW1[j][r / FE][r % FE] = (j == 0) ? m1W1[r] : hm1W[(j - 1) * FE * FE + r];
    }
    for (int t = tid; t < NL * FE; t += blockDim.x) {
        int j = t / FE, r = t % FE;
        sb1[j][r] = (j == 0) ? m1b1[r] : hm1b[(j - 1) * FE + r];
        sW2[j][r] = (j == 0) ? m2W1[r] : hm2W[(j - 1) * FE + r];
    }
    for (int t = tid; t < NL; t += blockDim.x)
        sb2[t] = (t == 0) ? m2b1[0] : hm2b[t - 1];
    __syncthreads();

    int p = blockIdx.x * blockDim.x + tid;
    if (p >= NE) return;
    int4 cs = g_cs[p];
    int srcn = cs.x, e = cs.y, dstn = cs.z;
    const float4* row = (const float4*)(ea + (size_t)e * FE);
    float4 v0 = row[0], v1 = row[1], v2 = row[2], v3 = row[3];
    ull ap[FE];
    ap[0]=pk2(v0.x,v0.x); ap[1]=pk2(v0.y,v0.y); ap[2]=pk2(v0.z,v0.z); ap[3]=pk2(v0.w,v0.w);
    ap[4]=pk2(v1.x,v1.x); ap[5]=pk2(v1.y,v1.y); ap[6]=pk2(v1.z,v1.z); ap[7]=pk2(v1.w,v1.w);
    ap[8]=pk2(v2.x,v2.x); ap[9]=pk2(v2.y,v2.y); ap[10]=pk2(v2.z,v2.z); ap[11]=pk2(v2.w,v2.w);
    ap[12]=pk2(v3.x,v3.x); ap[13]=pk2(v3.y,v3.y); ap[14]=pk2(v3.z,v3.z); ap[15]=pk2(v3.w,v3.w);

    #pragma unroll 1
    for (int j = 0; j < NL; j++) {
        ull h[8];
        #pragma unroll
        for (int i = 0; i < 8; i++) h[i] = pk2(sb1[j][2 * i], sb1[j][2 * i + 1]);
        #pragma unroll
        for (int k = 0; k < FE; k++) {
            ulonglong2 w01 = *(const ulonglong2*)&sW1[j][k][0];
            ulonglong2 w23 = *(const ulonglong2*)&sW1[j][k][4];
            ulonglong2 w45 = *(const ulonglong2*)&sW1[j][k][8];
            ulonglong2 w67 = *(const ulonglong2*)&sW1[j][k][12];
            fma2(h[0], ap[k], w01.x); fma2(h[1], ap[k], w01.y);
            fma2(h[2], ap[k], w23.x); fma2(h[3], ap[k], w23.y);
            fma2(h[4], ap[k], w45.x); fma2(h[5], ap[k], w45.y);
            fma2(h[6], ap[k], w67.x); fma2(h[7], ap[k], w67.y);
        }
        float out = sb2[j];
        #pragma unroll
        for (int i = 0; i < 8; i++) {
            float2 hv = upk(h[i]);
            out += fmaxf(hv.x, 0.0f) * sW2[j][2 * i];
            out += fmaxf(hv.y, 0.0f) * sW2[j][2 * i + 1];
        }
        float ew = 1.0f / (1.0f + __expf(-out));
        g_se[(size_t)j * NE + p] = make_int2(srcn, __float_as_int(ew));
        atomicAdd(&g_degacc[(size_t)j * NN + dstn], ew);
    }
}

// dis = rsqrt(1 + degacc)
__global__ void k_dis() {
    int t = blockIdx.x * blockDim.x + threadIdx.x;
    if (t < NL * NN) g_dis[t] = rsqrtf(1.0f + g_degacc[t]);
}

// ---------------- per-layer: GEMM (128-row tile, fp16 Ws, f32x2 math, fp16 out) ----------------
#define AST 132
template <bool BN>
__global__ void __launch_bounds__(256) k_gemm(const float* __restrict__ Xin,
                                              const float* __restrict__ W, int j)
{
    __shared__ float  As[64 * AST];      // 33792 B, [feat][row], rows 0..127
    __shared__ __half Wh[64 * 64];       // 8192 B
    __shared__ float  sdis[128];
    __shared__ float  smu[CH], sinv[CH];
    int tid = threadIdx.x;
    if (BN) {
        if (tid < CH) {
            double s1 = 0.0, s2 = 0.0;
            #pragma unroll
            for (int s = 0; s < NSLOT; s++) {
                s1 += g_stats2[j][s][0][tid];
                s2 += g_stats2[j][s][1][tid];
            }
            double mu = s1 / (double)NN;
            double var = s2 / (double)NN - mu * mu;
            smu[tid] = (float)mu;
            sinv[tid] = rsqrtf((float)var + 1e-5f);
        }
        __syncthreads();
    }
    int row0 = blockIdx.x * 128;
    for (int t = tid; t < 4096; t += 256) Wh[t] = __float2half(W[t]);
    if (tid < 128) {
        int gr = row0 + tid;
        sdis[tid] = (gr < NN) ? g_dis[(size_t)j * NN + gr] : 0.0f;
    }
    // As fill: 128 rows x 64 cols, 4 elements per thread-iter
    for (int t = tid; t < 2048; t += 256) {
        int r = t >> 4, c4 = (t & 15) * 4;
        int gr = row0 + r;
        float v0 = 0.f, v1 = 0.f, v2 = 0.f, v3 = 0.f;
        if (gr < NN) {
            if (BN) {
                uint2 q = *(const uint2*)&g_curh[(size_t)gr * CH + c4];
                float2 f0 = __half22float2(*(__half2*)&q.x);
                float2 f1 = __half22float2(*(__half2*)&q.y);
                v0 = fmaxf((f0.x - smu[c4])     * sinv[c4],     0.f);
                v1 = fmaxf((f0.y - smu[c4 + 1]) * sinv[c4 + 1], 0.f);
                v2 = fmaxf((f1.x - smu[c4 + 2]) * sinv[c4 + 2], 0.f);
                v3 = fmaxf((f1.y - smu[c4 + 3]) * sinv[c4 + 3], 0.f);
            } else {
                float4 f = *(const float4*)&Xin[(size_t)gr * CH + c4];
                v0 = f.x; v1 = f.y; v2 = f.z; v3 = f.w;
            }
        }
        As[(c4)     * AST + r] = v0;
        As[(c4 + 1) * AST + r] = v1;
        As[(c4 + 2) * AST + r] = v2;
        As[(c4 + 3) * AST + r] = v3;
    }
    __syncthreads();

    int ci = tid & 15, ri = tid >> 4;     // 16 col-groups x 16 row-groups (8 rows each)
    const float* Asr = As + ri * 8;
    ull acc[4][4];
    #pragma unroll
    for (int a = 0; a < 4; a++)
        #pragma unroll
        for (int b = 0; b < 4; b++) acc[a][b] = 0ull;

    #pragma unroll 8
    for (int k = 0; k < 64; k++) {
        ulonglong2 a01 = *(const ulonglong2*)(Asr + k * AST);
        ulonglong2 a23 = *(const ulonglong2*)(Asr + k * AST + 4);
        uint2 wq = *(const uint2*)(Wh + k * 64 + ci * 4);
        float2 bf0 = __half22float2(*(__half2*)&wq.x);
        float2 bf1 = __half22float2(*(__half2*)&wq.y);
        ull b0 = pk2(bf0.x, bf0.x), b1 = pk2(bf0.y, bf0.y);
        ull b2 = pk2(bf1.x, bf1.x), b3 = pk2(bf1.y, bf1.y);
        fma2(acc[0][0], a01.x, b0); fma2(acc[0][1], a01.x, b1);
        fma2(acc[0][2], a01.x, b2); fma2(acc[0][3], a01.x, b3);
        fma2(acc[1][0], a01.y, b0); fma2(acc[1][1], a01.y, b1);
        fma2(acc[1][2], a01.y, b2); fma2(acc[1][3], a01.y, b3);
        fma2(acc[2][0], a23.x, b0); fma2(acc[2][1], a23.x, b1);
        fma2(acc[2][2], a23.x, b2); fma2(acc[2][3], a23.x, b3);
        fma2(acc[3][0], a23.y, b0); fma2(acc[3][1], a23.y, b1);
        fma2(acc[3][2], a23.y, b2); fma2(acc[3][3], a23.y, b3);
    }

    #pragma unroll
    for (int p = 0; p < 4; p++) {
        float2 c0 = upk(acc[p][0]), c1 = upk(acc[p][1]);
        float2 c2 = upk(acc[p][2]), c3 = upk(acc[p][3]);
        int r0 = ri * 8 + 2 * p, r1 = r0 + 1;
        int gr0 = row0 + r0, gr1 = row0 + r1;
        if (gr0 < NN) {
            float d = sdis[r0];
            __half2 h01 = __floats2half2_rn(c0.x * d, c1.x * d);
            __half2 h23 = __floats2half2_rn(c2.x * d, c3.x * d);
            *(uint2*)&g_gbuf[(size_t)gr0 * CH + ci * 4] =
                make_uint2(*(unsigned*)&h01, *(unsigned*)&h23);
        }
        if (gr1 < NN) {
            float d = sdis[r1];
            __half2 h01 = __floats2half2_rn(c0.y * d, c1.y * d);
            __half2 h23 = __floats2half2_rn(c2.y * d, c3.y * d);
            *(uint2*)&g_gbuf[(size_t)gr1 * CH + ci * 4] =
                make_uint2(*(unsigned*)&h01, *(unsigned*)&h23);
        }
    }
}

// ---------------- per-layer: aggregation (+fused next-layer BN stats) ----------------
__global__ void __launch_bounds__(256) k_agg(const float* __restrict__ bias,
                                             int j, int mode, int statj)
{
    __shared__ float sst[2][8][CH];
    int wid = threadIdx.x >> 5;
    int gw = blockIdx.x * 8 + wid;
    int lane = threadIdx.x & 31;
    int node = gw;
    bool valid = (node < NN);
    int p0 = 0, p1 = 0;
    if (valid) { p0 = rp(node); p1 = rp(node + 1); }
    int eo = lane >> 3, cg = lane & 7;
    const int2* __restrict__ sej = g_se + (size_t)j * NE;
    float acc[8];
    #pragma unroll
    for (int i = 0; i < 8; i++) acc[i] = 0.0f;
    int p = p0 + eo;
    for (; p + 12 < p1; p += 16) {
        int2 e0 = sej[p], e1 = sej[p + 4], e2 = sej[p + 8], e3 = sej[p + 12];
        uint4 q0 = *(const uint4*)(g_gbuf + (size_t)e0.x * CH + cg * 8);
        uint4 q1 = *(const uint4*)(g_gbuf + (size_t)e1.x * CH + cg * 8);
        uint4 q2 = *(const uint4*)(g_gbuf + (size_t)e2.x * CH + cg * 8);
        uint4 q3 = *(const uint4*)(g_gbuf + (size_t)e3.x * CH + cg * 8);
        acc8(acc, __int_as_float(e0.y), q0);
        acc8(acc, __int_as_float(e1.y), q1);
        acc8(acc, __int_as_float(e2.y), q2);
        acc8(acc, __int_as_float(e3.y), q3);
    }
    for (; p + 4 < p1; p += 8) {
        int2 e0 = sej[p], e1 = sej[p + 4];
        uint4 q0 = *(const uint4*)(g_gbuf + (size_t)e0.x * CH + cg * 8);
        uint4 q1 = *(const uint4*)(g_gbuf + (size_t)e1.x * CH + cg * 8);
        acc8(acc, __int_as_float(e0.y), q0);
        acc8(acc, __int_as_float(e1.y), q1);
    }
    if (p < p1) {
        int2 e = sej[p];
        uint4 q = *(const uint4*)(g_gbuf + (size_t)e.x * CH + cg * 8);
        acc8(acc, __int_as_float(e.y), q);
    }
    #pragma unroll
    for (int i = 0; i < 8; i++) {
        acc[i] += __shfl_xor_sync(0xffffffffu, acc[i], 8);
        acc[i] += __shfl_xor_sync(0xffffffffu, acc[i], 16);
    }
    float n[8];
    bool writer = valid && (eo == 0);
    if (writer) {
        float bres[8];
        *(float4*)&bres[0] = *(const float4*)&bias[cg * 8];
        *(float4*)&bres[4] = *(const float4*)&bias[cg * 8 + 4];
        size_t off = (size_t)node * CH + cg * 8;
        uint4 qs = *(const uint4*)(g_gbuf + off);
        float sf[8];
        {
            float2 f0 = __half22float2(*(__half2*)&qs.x);
            float2 f1 = __half22float2(*(__half2*)&qs.y);
            float2 f2 = __half22float2(*(__half2*)&qs.z);
            float2 f3 = __half22float2(*(__half2*)&qs.w);
            sf[0]=f0.x; sf[1]=f0.y; sf[2]=f1.x; sf[3]=f1.y;
            sf[4]=f2.x; sf[5]=f2.y; sf[6]=f3.x; sf[7]=f3.y;
        }
        float dd = g_dis[(size_t)j * NN + node];
        float v[8];
        #pragma unroll
        for (int i = 0; i < 8; i++)
            v[i] = (acc[i] + sf[i]) * dd + bres[i];
        if (mode == 2) {
            float4 s0 = *(const float4*)&g_S[off];
            float4 s1 = *(const float4*)&g_S[off + 4];
            n[0] = v[0] + s0.x; n[1] = v[1] + s0.y; n[2] = v[2] + s0.z; n[3] = v[3] + s0.w;
            n[4] = v[4] + s1.x; n[5] = v[5] + s1.y; n[6] = v[6] + s1.z; n[7] = v[7] + s1.w;
            *(float4*)&g_S[off]     = make_float4(s0.x + n[0], s0.y + n[1], s0.z + n[2], s0.w + n[3]);
            *(float4*)&g_S[off + 4] = make_float4(s1.x + n[4], s1.y + n[5], s1.z + n[6], s1.w + n[7]);
        } else {
            #pragma unroll
            for (int i = 0; i < 8; i++) n[i] = v[i];
            if (mode == 1) {
                *(float4*)&g_S[off]     = make_float4(n[0], n[1], n[2], n[3]);
                *(float4*)&g_S[off + 4] = make_float4(n[4], n[5], n[6], n[7]);
            }
        }
        *(uint4*)&g_curh[off] = pack8h(n);
    }
    if (statj >= 0) {
        #pragma unroll
        for (int i = 0; i < 8; i++) {
            float val = writer ? n[i] : 0.0f;
            if (eo == 0) {
                sst[0][wid][cg * 8 + i] = val;
                sst[1][wid][cg * 8 + i] = val * val;
            }
        }
        __syncthreads();
        int tid = threadIdx.x;
        if (tid < CH) {
            float s1 = 0.0f, s2 = 0.0f;
            #pragma unroll
            for (int w = 0; w < 8; w++) { s1 += sst[0][w][tid]; s2 += sst[1][w][tid]; }
            int slot = blockIdx.x & (NSLOT - 1);
            atomicAdd(&g_stats2[statj][slot][0][tid], (double)s1);
            atomicAdd(&g_stats2[statj][slot][1][tid], (double)s2);
        }
    }
}

// ---------------- readout ----------------
__global__ void k_pool(const int* __restrict__ batch) {
    int t = blockIdx.x * blockDim.x + threadIdx.x;
    if (t >= NCHUNK * CH) return;
    int chunk = t >> 6, c = t & 63;
    int n0 = chunk * 16, n1 = min(n0 + 16, NN);
    int curb = batch[n0];
    float m = -1.0f;
    for (int nidx = n0; nidx < n1; nidx++) {
        int b = batch[nidx];
        if (b != curb) {
            atomicMax((int*)&g_pool[curb * CH + c], __float_as_int(fmaxf(m, 0.0f)));
            curb = b;
            m = -1.0f;
        }
        m = fmaxf(m, __half2float(g_curh[(size_t)nidx * CH + c]));
    }
    atomicMax((int*)&g_pool[curb * CH + c], __float_as_int(fmaxf(m, 0.0f)));
}

__global__ void k_final(const float* __restrict__ linW, const float* __restrict__ linb,
                        float* __restrict__ out)
{
    int g = blockIdx.x, c = threadIdx.x;
    float p = g_pool[g * CH + c];
    float v0 = p * linW[c * 2 + 0];
    float v1 = p * linW[c * 2 + 1];
    #pragma unroll
    for (int o = 16; o; o >>= 1) {
        v0 += __shfl_down_sync(0xffffffffu, v0, o);
        v1 += __shfl_down_sync(0xffffffffu, v1, o);
    }
    __shared__ float s0[2], s1[2];
    if ((c & 31) == 0) { s0[c >> 5] = v0; s1[c >> 5] = v1; }
    __syncthreads();
    if (c == 0) {
        out[g * 2 + 0] = s0[0] + s0[1] + linb[0];
        out[g * 2 + 1] = s1[0] + s1[1] + linb[1];
    }
}

// ---------------- host ----------------
extern "C" void kernel_launch(void* const* d_in, const int* in_sizes, int n_in,
                              void* d_out, int out_size)
{
    const float* x     = (const float*)d_in[0];
    const int*   ei    = (const int*)d_in[1];
    const int*   srcp  = ei;
    const int*   dstp  = ei + NE;
    const int*   batch = (const int*)d_in[2];
    int base = (in_sizes[3] == 1) ? 4 : 3;
    const float* edge_attr = (const float*)d_in[base + 0];
    const float* Wlin1 = (const float*)d_in[base + 1];
    const float* bias1 = (const float*)d_in[base + 2];
    const float* m1W1  = (const float*)d_in[base + 3];
    const float* m1b1  = (const float*)d_in[base + 4];
    const float* m2W1  = (const float*)d_in[base + 5];
    const float* m2b1  = (const float*)d_in[base + 6];
    const float* hWlin = (const float*)d_in[base + 7];
    const float* hbias = (const float*)d_in[base + 8];
    const float* hm1W  = (const float*)d_in[base + 9];
    const float* hm1b  = (const float*)d_in[base + 10];
    const float* hm2W  = (const float*)d_in[base + 11];
    const float* hm2b  = (const float*)d_in[base + 12];
    const float* linW  = (const float*)d_in[base + 13];
    const float* linb  = (const float*)d_in[base + 14];

    void* p_cursor = nullptr;
    void* p_stats  = nullptr;
    void* p_pool   = nullptr;
    void* p_deg    = nullptr;
    cudaGetSymbolAddress(&p_cursor, g_cursor);
    cudaGetSymbolAddress(&p_stats,  g_stats2);
    cudaGetSymbolAddress(&p_pool,   g_pool);
    cudaGetSymbolAddress(&p_deg,    g_degacc);
    cudaMemsetAsync(p_cursor, 0, sizeof(int) * NN);
    cudaMemsetAsync(p_stats,  0, sizeof(double) * NL * NSLOT * 2 * CH);
    cudaMemsetAsync(p_pool,   0, sizeof(float) * NG * CH);
    cudaMemsetAsync(p_deg,    0, sizeof(float) * NL * NN);

    k_count<<<(NE + 255) / 256, 256>>>(dstp);
    k_scanA<<<SCAN_NB, 256>>>();
    k_scanB<<<1, 256>>>();
    k_fill<<<(NE + 255) / 256, 256>>>(srcp, dstp);
    k_mlp<<<(NE + 255) / 256, 256>>>(edge_attr, m1W1, m1b1, m2W1, m2b1,
                                     hm1W, hm1b, hm2W, hm2b);
    k_dis<<<(NL * NN + 255) / 256, 256>>>();

    for (int j = 0; j < NL; j++) {
        if (j == 0) {
            k_gemm<false><<<(NN + 127) / 128, 256>>>(x, Wlin1, 0);
        } else {
            k_gemm<true><<<(NN + 127) / 128, 256>>>(x, hWlin + (size_t)(j - 1) * CH * CH, j);
        }
        int mode = (j == 0) ? 1 : ((j % 2 == 0) ? 2 : 0);
        int statj = (j < NL - 1) ? (j + 1) : -1;
        const float* bias = (j == 0) ? bias1 : hbias + (size_t)(j - 1) * CH;
        k_agg<<<(NN + 7) / 8, 256>>>(bias, j, mode, statj);
    }

    k_pool<<<(NCHUNK * CH + 255) / 256, 256>>>(batch);
    k_final<<<NG, 64>>>(linW, linb, (float*)d_out);
    (void)n_in; (void)out_size;
}

// round 15
// speedup vs baseline: 1.0948x; 1.0948x over previous
#include <cuda_runtime.h>
#include <cuda_fp16.h>
#include <math.h>

#define NN 50000
#define NE 800000
#define CH 64
#define FE 16
#define NL 13          // conv1 + 12 hidden
#define NG 500
#define NCHUNK ((NN + 15) / 16)
#define SCAN_NB ((NN + 255) / 256)
#define NSLOT 8        // spread slots for stats atomics

typedef unsigned long long ull;

// ---------------- f32x2 helpers ----------------
__device__ __forceinline__ ull pk2(float x, float y) {
    ull r;
    asm("mov.b64 %0, {%1, %2};" : "=l"(r) : "r"(__float_as_uint(x)), "r"(__float_as_uint(y)));
    return r;
}
__device__ __forceinline__ void fma2(ull& d, ull a, ull b) {
    asm("fma.rn.f32x2 %0, %1, %2, %3;" : "=l"(d) : "l"(a), "l"(b), "l"(d));
}
__device__ __forceinline__ float2 upk(ull v) {
    unsigned lo, hi;
    asm("mov.b64 {%0, %1}, %2;" : "=r"(lo), "=r"(hi) : "l"(v));
    return make_float2(__uint_as_float(lo), __uint_as_float(hi));
}

// ---------------- scratch ----------------
__device__ int2   g_se[(size_t)NL * NE];     // (src, float-bits ew) per layer, CSR order
__device__ float  g_degacc[(size_t)NL * NN]; // weighted degree accumulators
__device__ float  g_dis[(size_t)NL * NN];
__device__ int    g_rowptr[NN + 1];          // per-block-local exclusive; global = + boff[i>>8]
__device__ int    g_cursor[NN];
__device__ int4   g_cs[NE];                  // (src, eid, dst, 0) per CSR slot
__device__ int    g_bsum[SCAN_NB + 1];
__device__ int    g_boff[SCAN_NB + 1];
__device__ __half g_gbuf[(size_t)NN * CH];   // fp16 gather buffer
__device__ __half g_curh[(size_t)NN * CH];   // fp16 current features
__device__ float  g_S[(size_t)NN * CH];      // fp32 skip accumulator
__device__ double g_stats2[NL][NSLOT][2][CH];
__device__ float  g_pool[NG * CH];

// global rowptr accessor (i in [0, NN])
__device__ __forceinline__ int rp(int i) {
    if (i >= NN) return g_rowptr[NN];
    return g_rowptr[i] + g_boff[i >> 8];
}

// unpack 4 half2 (from uint4) scaled-accumulate
__device__ __forceinline__ void acc8(float* acc, float w, uint4 q) {
    float2 f0 = __half22float2(*(__half2*)&q.x);
    float2 f1 = __half22float2(*(__half2*)&q.y);
    float2 f2 = __half22float2(*(__half2*)&q.z);
    float2 f3 = __half22float2(*(__half2*)&q.w);
    acc[0] += w * f0.x; acc[1] += w * f0.y;
    acc[2] += w * f1.x; acc[3] += w * f1.y;
    acc[4] += w * f2.x; acc[5] += w * f2.y;
    acc[6] += w * f3.x; acc[7] += w * f3.y;
}

__device__ __forceinline__ uint4 pack8h(const float* v) {
    __half2 h0 = __floats2half2_rn(v[0], v[1]);
    __half2 h1 = __floats2half2_rn(v[2], v[3]);
    __half2 h2 = __floats2half2_rn(v[4], v[5]);
    __half2 h3 = __floats2half2_rn(v[6], v[7]);
    return make_uint4(*(unsigned*)&h0, *(unsigned*)&h1, *(unsigned*)&h2, *(unsigned*)&h3);
}

// ---------------- setup ----------------
__global__ void k_count(const int* __restrict__ dst) {
    int e = blockIdx.x * blockDim.x + threadIdx.x;
    if (e < NE) atomicAdd(&g_cursor[dst[e]], 1);
}

__device__ __forceinline__ int blockscan256(int v, int* warpsums) {
    int lane = threadIdx.x & 31, wid = threadIdx.x >> 5;
    int x = v;
    #pragma unroll
    for (int o = 1; o < 32; o <<= 1) {
        int t = __shfl_up_sync(0xffffffffu, x, o);
        if (lane >= o) x += t;
    }
    if (lane == 31) warpsums[wid] = x;
    __syncthreads();
    if (wid == 0 && lane < 8) {
        int w = warpsums[lane];
        #pragma unroll
        for (int o = 1; o < 8; o <<= 1) {
            int t = __shfl_up_sync(0xffu, w, o);
            if (lane >= o) w += t;
        }
        warpsums[lane] = w;
    }
    __syncthreads();
    return x + (wid > 0 ? warpsums[wid - 1] : 0);
}

__global__ void k_scanA() {
    __shared__ int ws[8];
    int i = blockIdx.x * 256 + threadIdx.x;
    int v = (i < NN) ? g_cursor[i] : 0;
    int incl = blockscan256(v, ws);
    if (i < NN) {
        g_rowptr[i] = incl - v;
        g_cursor[i] = incl - v;
    }
    if (threadIdx.x == 255) g_bsum[blockIdx.x] = incl;
}

__global__ void k_scanB() {
    __shared__ int ws[8];
    int t = threadIdx.x;
    int v = (t < SCAN_NB) ? g_bsum[t] : 0;
    int incl = blockscan256(v, ws);
    if (t < SCAN_NB) g_boff[t] = incl - v;
    if (t == 255) g_rowptr[NN] = incl;
}

__global__ void k_fill(const int* __restrict__ src, const int* __restrict__ dst) {
    int e = blockIdx.x * blockDim.x + threadIdx.x;
    if (e < NE) {
        int d = dst[e];
        int pos = atomicAdd(&g_cursor[d], 1) + g_boff[d >> 8];
        g_cs[pos] = make_int4(src[e], e, d, 0);
    }
}

// ---------------- all-layers edge MLP: writes (src, ew) pairs + degree atomics ----------------
__global__ void __launch_bounds__(256) k_mlp(
    const float* __restrict__ ea,
    const float* __restrict__ m1W1, const float* __restrict__ m1b1,
    const float* __restrict__ m2W1, const float* __restrict__ m2b1,
    const float* __restrict__ hm1W, const float* __restrict__ hm1b,
    const float* __restrict__ hm2W, const float* __restrict__ hm2b)
{
    __shared__ float sW1[NL][FE][FE];
    __shared__ float sb1[NL][FE];
    __shared__ float sW2[NL][FE];
    __shared__ float sb2[NL];
    int tid = threadIdx.x;
    for (int t = tid; t < NL * FE * FE; t += blockDim.x) {
        int j = t / (FE * FE), r = t % (FE * FE);
        sW1[j][r / FE][r % FE] = (j == 0) ? m1W1[r] : hm1W[(j - 1) * FE * FE + r];
    }
    for (int t = tid; t < NL * FE; t += blockDim.x) {
        int j = t / FE, r = t % FE;
        sb1[j][r] = (j == 0) ? m1b1[r] : hm1b[(j - 1) * FE + r];
        sW2[j][r] = (j == 0) ? m2W1[r] : hm2W[(j - 1) * FE + r];
    }
    for (int t = tid; t < NL; t += blockDim.x)
        sb2[t] = (t == 0) ? m2b1[0] : hm2b[t - 1];
    __syncthreads();

    int p = blockIdx.x * blockDim.x + tid;
    if (p >= NE) return;
    int4 cs = g_cs[p];
    int srcn = cs.x, e = cs.y, dstn = cs.z;
    const float4* row = (const float4*)(ea + (size_t)e * FE);
    float4 v0 = row[0], v1 = row[1], v2 = row[2], v3 = row[3];
    ull ap[FE];
    ap[0]=pk2(v0.x,v0.x); ap[1]=pk2(v0.y,v0.y); ap[2]=pk2(v0.z,v0.z); ap[3]=pk2(v0.w,v0.w);
    ap[4]=pk2(v1.x,v1.x); ap[5]=pk2(v1.y,v1.y); ap[6]=pk2(v1.z,v1.z); ap[7]=pk2(v1.w,v1.w);
    ap[8]=pk2(v2.x,v2.x); ap[9]=pk2(v2.y,v2.y); ap[10]=pk2(v2.z,v2.z); ap[11]=pk2(v2.w,v2.w);
    ap[12]=pk2(v3.x,v3.x); ap[13]=pk2(v3.y,v3.y); ap[14]=pk2(v3.z,v3.z); ap[15]=pk2(v3.w,v3.w);

    #pragma unroll 1
    for (int j = 0; j < NL; j++) {
        ull h[8];
        #pragma unroll
        for (int i = 0; i < 8; i++) h[i] = pk2(sb1[j][2 * i], sb1[j][2 * i + 1]);
        #pragma unroll
        for (int k = 0; k < FE; k++) {
            ulonglong2 w01 = *(const ulonglong2*)&sW1[j][k][0];
            ulonglong2 w23 = *(const ulonglong2*)&sW1[j][k][4];
            ulonglong2 w45 = *(const ulonglong2*)&sW1[j][k][8];
            ulonglong2 w67 = *(const ulonglong2*)&sW1[j][k][12];
            fma2(h[0], ap[k], w01.x); fma2(h[1], ap[k], w01.y);
            fma2(h[2], ap[k], w23.x); fma2(h[3], ap[k], w23.y);
            fma2(h[4], ap[k], w45.x); fma2(h[5], ap[k], w45.y);
            fma2(h[6], ap[k], w67.x); fma2(h[7], ap[k], w67.y);
        }
        float out = sb2[j];
        #pragma unroll
        for (int i = 0; i < 8; i++) {
            float2 hv = upk(h[i]);
            out += fmaxf(hv.x, 0.0f) * sW2[j][2 * i];
            out += fmaxf(hv.y, 0.0f) * sW2[j][2 * i + 1];
        }
        float ew = 1.0f / (1.0f + __expf(-out));
        g_se[(size_t)j * NE + p] = make_int2(srcn, __float_as_int(ew));
        atomicAdd(&g_degacc[(size_t)j * NN + dstn], ew);
    }
}

// dis = rsqrt(1 + degacc)
__global__ void k_dis() {
    int t = blockIdx.x * blockDim.x + threadIdx.x;
    if (t < NL * NN) g_dis[t] = rsqrtf(1.0f + g_degacc[t]);
}

// ---------------- per-layer: GEMM (64-row tile, f32x2 math; fp16 in for BN path, fp16 out) ----------------
#define ASTRIDE 68
template <bool BN>
__global__ void __launch_bounds__(128) k_gemm(const float* __restrict__ Xin,
                                              const float* __restrict__ W, int j)
{
    __shared__ float As[64 * ASTRIDE];
    __shared__ float Ws[64 * 64];
    __shared__ float sdis[64];
    __shared__ float smu[CH], sinv[CH];
    int tid = threadIdx.x;
    if (BN) {
        if (tid < CH) {
            double s1 = 0.0, s2 = 0.0;
            #pragma unroll
            for (int s = 0; s < NSLOT; s++) {
                s1 += g_stats2[j][s][0][tid];
                s2 += g_stats2[j][s][1][tid];
            }
            double mu = s1 / (double)NN;
            double var = s2 / (double)NN - mu * mu;
            smu[tid] = (float)mu;
            sinv[tid] = rsqrtf((float)var + 1e-5f);
        }
        __syncthreads();
    }
    int row0 = blockIdx.x * 64;
    for (int t = tid; t < 4096; t += 128) Ws[t] = W[t];
    if (tid < 64) {
        int gr = row0 + tid;
        sdis[tid] = (gr < NN) ? g_dis[(size_t)j * NN + gr] : 0.0f;
    }
    // vectorized As fill: 64 rows x 16 col-groups of 4
    for (int t = tid; t < 1024; t += 128) {
        int r = t >> 4, c4 = (t & 15) * 4;
        int gr = row0 + r;
        float v0 = 0.f, v1 = 0.f, v2 = 0.f, v3 = 0.f;
        if (gr < NN) {
            if (BN) {
                uint2 q = *(const uint2*)&g_curh[(size_t)gr * CH + c4];
                float2 f0 = __half22float2(*(__half2*)&q.x);
                float2 f1 = __half22float2(*(__half2*)&q.y);
                v0 = fmaxf((f0.x - smu[c4])     * sinv[c4],     0.f);
                v1 = fmaxf((f0.y - smu[c4 + 1]) * sinv[c4 + 1], 0.f);
                v2 = fmaxf((f1.x - smu[c4 + 2]) * sinv[c4 + 2], 0.f);
                v3 = fmaxf((f1.y - smu[c4 + 3]) * sinv[c4 + 3], 0.f);
            } else {
                float4 f = *(const float4*)&Xin[(size_t)gr * CH + c4];
                v0 = f.x; v1 = f.y; v2 = f.z; v3 = f.w;
            }
        }
        As[(c4)     * ASTRIDE + r] = v0;
        As[(c4 + 1) * ASTRIDE + r] = v1;
        As[(c4 + 2) * ASTRIDE + r] = v2;
        As[(c4 + 3) * ASTRIDE + r] = v3;
    }
    __syncthreads();

    int ci = tid & 15, ri = tid >> 4;
    const float* Asr = As + ri * 8;
    const float* Wsc = Ws + ci * 4;
    ull acc[4][4];
    #pragma unroll
    for (int a = 0; a < 4; a++)
        #pragma unroll
        for (int b = 0; b < 4; b++) acc[a][b] = 0ull;

    #pragma unroll 8
    for (int k = 0; k < 64; k++) {
        ulonglong2 a01 = *(const ulonglong2*)(Asr + k * ASTRIDE);
        ulonglong2 a23 = *(const ulonglong2*)(Asr + k * ASTRIDE + 4);
        float4 b = *(const float4*)(Wsc + (size_t)k * 64);
        ull b0 = pk2(b.x, b.x), b1 = pk2(b.y, b.y);
        ull b2 = pk2(b.z, b.z), b3 = pk2(b.w, b.w);
        fma2(acc[0][0], a01.x, b0); fma2(acc[0][1], a01.x, b1);
        fma2(acc[0][2], a01.x, b2); fma2(acc[0][3], a01.x, b3);
        fma2(acc[1][0], a01.y, b0); fma2(acc[1][1], a01.y, b1);
        fma2(acc[1][2], a01.y, b2); fma2(acc[1][3], a01.y, b3);
        fma2(acc[2][0], a23.x, b0); fma2(acc[2][1], a23.x, b1);
        fma2(acc[2][2], a23.x, b2); fma2(acc[2][3], a23.x, b3);
        fma2(acc[3][0], a23.y, b0); fma2(acc[3][1], a23.y, b1);
        fma2(acc[3][2], a23.y, b2); fma2(acc[3][3], a23.y, b3);
    }

    #pragma unroll
    for (int p = 0; p < 4; p++) {
        float2 c0 = upk(acc[p][0]), c1 = upk(acc[p][1]);
        float2 c2 = upk(acc[p][2]), c3 = upk(acc[p][3]);
        int r0 = ri * 8 + 2 * p, r1 = r0 + 1;
        int gr0 = row0 + r0, gr1 = row0 + r1;
        if (gr0 < NN) {
            float d = sdis[r0];
            __half2 h01 = __floats2half2_rn(c0.x * d, c1.x * d);
            __half2 h23 = __floats2half2_rn(c2.x * d, c3.x * d);
            *(uint2*)&g_gbuf[(size_t)gr0 * CH + ci * 4] =
                make_uint2(*(unsigned*)&h01, *(unsigned*)&h23);
        }
        if (gr1 < NN) {
            float d = sdis[r1];
            __half2 h01 = __floats2half2_rn(c0.y * d, c1.y * d);
            __half2 h23 = __floats2half2_rn(c2.y * d, c3.y * d);
            *(uint2*)&g_gbuf[(size_t)gr1 * CH + ci * 4] =
                make_uint2(*(unsigned*)&h01, *(unsigned*)&h23);
        }
    }
}

// ---------------- per-layer: aggregation (+fused next-layer BN stats) ----------------
__global__ void __launch_bounds__(256) k_agg(const float* __restrict__ bias,
                                             int j, int mode, int statj)
{
    __shared__ float sst[2][8][CH];
    int wid = threadIdx.x >> 5;
    int gw = blockIdx.x * 8 + wid;
    int lane = threadIdx.x & 31;
    int node = gw;
    bool valid = (node < NN);
    int p0 = 0, p1 = 0;
    if (valid) { p0 = rp(node); p1 = rp(node + 1); }
    int eo = lane >> 3, cg = lane & 7;
    const int2* __restrict__ sej = g_se + (size_t)j * NE;
    float acc[8];
    #pragma unroll
    for (int i = 0; i < 8; i++) acc[i] = 0.0f;
    int p = p0 + eo;
    for (; p + 12 < p1; p += 16) {
        int2 e0 = sej[p], e1 = sej[p + 4], e2 = sej[p + 8], e3 = sej[p + 12];
        uint4 q0 = *(const uint4*)(g_gbuf + (size_t)e0.x * CH + cg * 8);
        uint4 q1 = *(const uint4*)(g_gbuf + (size_t)e1.x * CH + cg * 8);
        uint4 q2 = *(const uint4*)(g_gbuf + (size_t)e2.x * CH + cg * 8);
        uint4 q3 = *(const uint4*)(g_gbuf + (size_t)e3.x * CH + cg * 8);
        acc8(acc, __int_as_float(e0.y), q0);
        acc8(acc, __int_as_float(e1.y), q1);
        acc8(acc, __int_as_float(e2.y), q2);
        acc8(acc, __int_as_float(e3.y), q3);
    }
    for (; p + 4 < p1; p += 8) {
        int2 e0 = sej[p], e1 = sej[p + 4];
        uint4 q0 = *(const uint4*)(g_gbuf + (size_t)e0.x * CH + cg * 8);
        uint4 q1 = *(const uint4*)(g_gbuf + (size_t)e1.x * CH + cg * 8);
        acc8(acc, __int_as_float(e0.y), q0);
        acc8(acc, __int_as_float(e1.y), q1);
    }
    if (p < p1) {
        int2 e = sej[p];
        uint4 q = *(const uint4*)(g_gbuf + (size_t)e.x * CH + cg * 8);
        acc8(acc, __int_as_float(e.y), q);
    }
    #pragma unroll
    for (int i = 0; i < 8; i++) {
        acc[i] += __shfl_xor_sync(0xffffffffu, acc[i], 8);
        acc[i] += __shfl_xor_sync(0xffffffffu, acc[i], 16);
    }
    float n[8];
    bool writer = valid && (eo == 0);
    if (writer) {
        float bres[8];
        *(float4*)&bres[0] = *(const float4*)&bias[cg * 8];
        *(float4*)&bres[4] = *(const float4*)&bias[cg * 8 + 4];
        size_t off = (size_t)node * CH + cg * 8;
        uint4 qs = *(const uint4*)(g_gbuf + off);
        float sf[8];
        {
            float2 f0 = __half22float2(*(__half2*)&qs.x);
            float2 f1 = __half22float2(*(__half2*)&qs.y);
            float2 f2 = __half22float2(*(__half2*)&qs.z);
            float2 f3 = __half22float2(*(__half2*)&qs.w);
            sf[0]=f0.x; sf[1]=f0.y; sf[2]=f1.x; sf[3]=f1.y;
            sf[4]=f2.x; sf[5]=f2.y; sf[6]=f3.x; sf[7]=f3.y;
        }
        float dd = g_dis[(size_t)j * NN + node];
        float v[8];
        #pragma unroll
        for (int i = 0; i < 8; i++)
            v[i] = (acc[i] + sf[i]) * dd + bres[i];
        if (mode == 2) {
            float4 s0 = *(const float4*)&g_S[off];
            float4 s1 = *(const float4*)&g_S[off + 4];
            n[0] = v[0] + s0.x; n[1] = v[1] + s0.y; n[2] = v[2] + s0.z; n[3] = v[3] + s0.w;
            n[4] = v[4] + s1.x; n[5] = v[5] + s1.y; n[6] = v[6] + s1.z; n[7] = v[7] + s1.w;
            *(float4*)&g_S[off]     = make_float4(s0.x + n[0], s0.y + n[1], s0.z + n[2], s0.w + n[3]);
            *(float4*)&g_S[off + 4] = make_float4(s1.x + n[4], s1.y + n[5], s1.z + n[6], s1.w + n[7]);
        } else {
            #pragma unroll
            for (int i = 0; i < 8; i++) n[i] = v[i];
            if (mode == 1) {
                *(float4*)&g_S[off]     = make_float4(n[0], n[1], n[2], n[3]);
                *(float4*)&g_S[off + 4] = make_float4(n[4], n[5], n[6], n[7]);
            }
        }
        *(uint4*)&g_curh[off] = pack8h(n);
    }
    if (statj >= 0) {
        #pragma unroll
        for (int i = 0; i < 8; i++) {
            float val = writer ? n[i] : 0.0f;
            if (eo == 0) {
                sst[0][wid][cg * 8 + i] = val;
                sst[1][wid][cg * 8 + i] = val * val;
            }
        }
        __syncthreads();
        int tid = threadIdx.x;
        if (tid < CH) {
            float s1 = 0.0f, s2 = 0.0f;
            #pragma unroll
            for (int w = 0; w < 8; w++) { s1 += sst[0][w][tid]; s2 += sst[1][w][tid]; }
            int slot = blockIdx.x & (NSLOT - 1);
            atomicAdd(&g_stats2[statj][slot][0][tid], (double)s1);
            atomicAdd(&g_stats2[statj][slot][1][tid], (double)s2);
        }
    }
}

// ---------------- readout ----------------
__global__ void k_pool(const int* __restrict__ batch) {
    int t = blockIdx.x * blockDim.x + threadIdx.x;
    if (t >= NCHUNK * CH) return;
    int chunk = t >> 6, c = t & 63;
    int n0 = chunk * 16, n1 = min(n0 + 16, NN);
    int curb = batch[n0];
    float m = -1.0f;
    for (int nidx = n0; nidx < n1; nidx++) {
        int b = batch[nidx];
        if (b != curb) {
            atomicMax((int*)&g_pool[curb * CH + c], __float_as_int(fmaxf(m, 0.0f)));
            curb = b;
            m = -1.0f;
        }
        m = fmaxf(m, __half2float(g_curh[(size_t)nidx * CH + c]));
    }
    atomicMax((int*)&g_pool[curb * CH + c], __float_as_int(fmaxf(m, 0.0f)));
}

__global__ void k_final(const float* __restrict__ linW, const float* __restrict__ linb,
                        float* __restrict__ out)
{
    int g = blockIdx.x, c = threadIdx.x;
    float p = g_pool[g * CH + c];
    float v0 = p * linW[c * 2 + 0];
    float v1 = p * linW[c * 2 + 1];
    #pragma unroll
    for (int o = 16; o; o >>= 1) {
        v0 += __shfl_down_sync(0xffffffffu, v0, o);
        v1 += __shfl_down_sync(0xffffffffu, v1, o);
    }
    __shared__ float s0[2], s1[2];
    if ((c & 31) == 0) { s0[c >> 5] = v0; s1[c >> 5] = v1; }
    __syncthreads();
    if (c == 0) {
        out[g * 2 + 0] = s0[0] + s0[1] + linb[0];
        out[g * 2 + 1] = s1[0] + s1[1] + linb[1];
    }
}

// ---------------- host ----------------
extern "C" void kernel_launch(void* const* d_in, const int* in_sizes, int n_in,
                              void* d_out, int out_size)
{
    const float* x     = (const float*)d_in[0];
    const int*   ei    = (const int*)d_in[1];
    const int*   srcp  = ei;
    const int*   dstp  = ei + NE;
    const int*   batch = (const int*)d_in[2];
    int base = (in_sizes[3] == 1) ? 4 : 3;
    const float* edge_attr = (const float*)d_in[base + 0];
    const float* Wlin1 = (const float*)d_in[base + 1];
    const float* bias1 = (const float*)d_in[base + 2];
    const float* m1W1  = (const float*)d_in[base + 3];
    const float* m1b1  = (const float*)d_in[base + 4];
    const float* m2W1  = (const float*)d_in[base + 5];
    const float* m2b1  = (const float*)d_in[base + 6];
    const float* hWlin = (const float*)d_in[base + 7];
    const float* hbias = (const float*)d_in[base + 8];
    const float* hm1W  = (const float*)d_in[base + 9];
    const float* hm1b  = (const float*)d_in[base + 10];
    const float* hm2W  = (const float*)d_in[base + 11];
    const float* hm2b  = (const float*)d_in[base + 12];
    const float* linW  = (const float*)d_in[base + 13];
    const float* linb  = (const float*)d_in[base + 14];

    void* p_cursor = nullptr;
    void* p_stats  = nullptr;
    void* p_pool   = nullptr;
    void* p_deg    = nullptr;
    cudaGetSymbolAddress(&p_cursor, g_cursor);
    cudaGetSymbolAddress(&p_stats,  g_stats2);
    cudaGetSymbolAddress(&p_pool,   g_pool);
    cudaGetSymbolAddress(&p_deg,    g_degacc);
    cudaMemsetAsync(p_cursor, 0, sizeof(int) * NN);
    cudaMemsetAsync(p_stats,  0, sizeof(double) * NL * NSLOT * 2 * CH);
    cudaMemsetAsync(p_pool,   0, sizeof(float) * NG * CH);
    cudaMemsetAsync(p_deg,    0, sizeof(float) * NL * NN);

    k_count<<<(NE + 255) / 256, 256>>>(dstp);
    k_scanA<<<SCAN_NB, 256>>>();
    k_scanB<<<1, 256>>>();
    k_fill<<<(NE + 255) / 256, 256>>>(srcp, dstp);
    k_mlp<<<(NE + 255) / 256, 256>>>(edge_attr, m1W1, m1b1, m2W1, m2b1,
                                     hm1W, hm1b, hm2W, hm2b);
    k_dis<<<(NL * NN + 255) / 256, 256>>>();

    for (int j = 0; j < NL; j++) {
        if (j == 0) {
            k_gemm<false><<<(NN + 63) / 64, 128>>>(x, Wlin1, 0);
        } else {
            k_gemm<true><<<(NN + 63) / 64, 128>>>(x, hWlin + (size_t)(j - 1) * CH * CH, j);
        }
        int mode = (j == 0) ? 1 : ((j % 2 == 0) ? 2 : 0);
        int statj = (j < NL - 1) ? (j + 1) : -1;
        const float* bias = (j == 0) ? bias1 : hbias + (size_t)(j - 1) * CH;
        k_agg<<<(NN + 7) / 8, 256>>>(bias, j, mode, statj);
    }

    k_pool<<<(NCHUNK * CH + 255) / 256, 256>>>(batch);
    k_final<<<NG, 64>>>(linW, linb, (float*)d_out);
    (void)n_in; (void)out_size;
}

// round 16
// speedup vs baseline: 1.1648x; 1.0639x over previous
#include <cuda_runtime.h>
#include <cuda_fp16.h>
#include <math.h>

#define NN 50000
#define NE 800000
#define CH 64
#define FE 16
#define NL 13          // conv1 + 12 hidden
#define NG 500
#define NCHUNK ((NN + 15) / 16)
#define SCAN_NB ((NN + 255) / 256)
#define NSLOT 8        // spread slots for stats atomics

typedef unsigned long long ull;

// PDL: dependent grid may start early; wait here for predecessor's writes.
#define PDL_SYNC() do { cudaGridDependencySynchronize(); cudaTriggerProgrammaticLaunchCompletion(); } while (0)

// ---------------- f32x2 helpers ----------------
__device__ __forceinline__ ull pk2(float x, float y) {
    ull r;
    asm("mov.b64 %0, {%1, %2};" : "=l"(r) : "r"(__float_as_uint(x)), "r"(__float_as_uint(y)));
    return r;
}
__device__ __forceinline__ void fma2(ull& d, ull a, ull b) {
    asm("fma.rn.f32x2 %0, %1, %2, %3;" : "=l"(d) : "l"(a), "l"(b), "l"(d));
}
__device__ __forceinline__ float2 upk(ull v) {
    unsigned lo, hi;
    asm("mov.b64 {%0, %1}, %2;" : "=r"(lo), "=r"(hi) : "l"(v));
    return make_float2(__uint_as_float(lo), __uint_as_float(hi));
}

// ---------------- scratch ----------------
__device__ int2   g_se[(size_t)NL * NE];     // (src, float-bits ew) per layer, CSR order
__device__ float  g_degacc[(size_t)NL * NN]; // weighted degree accumulators
__device__ float  g_dis[(size_t)NL * NN];
__device__ int    g_rowptr[NN + 1];          // per-block-local exclusive; global = + boff[i>>8]
__device__ int    g_cursor[NN];
__device__ int4   g_cs[NE];                  // (src, eid, dst, 0) per CSR slot
__device__ int    g_bsum[SCAN_NB + 1];
__device__ int    g_boff[SCAN_NB + 1];
__device__ __half g_gbuf[(size_t)NN * CH];   // fp16 gather buffer
__device__ __half g_curh[(size_t)NN * CH];   // fp16 current features
__device__ float  g_S[(size_t)NN * CH];      // fp32 skip accumulator
__device__ double g_stats2[NL][NSLOT][2][CH];
__device__ float  g_pool[NG * CH];

// global rowptr accessor (i in [0, NN])
__device__ __forceinline__ int rp(int i) {
    if (i >= NN) return g_rowptr[NN];
    return g_rowptr[i] + g_boff[i >> 8];
}

// unpack 4 half2 (from uint4) scaled-accumulate
__device__ __forceinline__ void acc8(float* acc, float w, uint4 q) {
    float2 f0 = __half22float2(*(__half2*)&q.x);
    float2 f1 = __half22float2(*(__half2*)&q.y);
    float2 f2 = __half22float2(*(__half2*)&q.z);
    float2 f3 = __half22float2(*(__half2*)&q.w);
    acc[0] += w * f0.x; acc[1] += w * f0.y;
    acc[2] += w * f1.x; acc[3] += w * f1.y;
    acc[4] += w * f2.x; acc[5] += w * f2.y;
    acc[6] += w * f3.x; acc[7] += w * f3.y;
}

__device__ __forceinline__ uint4 pack8h(const float* v) {
    __half2 h0 = __floats2half2_rn(v[0], v[1]);
    __half2 h1 = __floats2half2_rn(v[2], v[3]);
    __half2 h2 = __floats2half2_rn(v[4], v[5]);
    __half2 h3 = __floats2half2_rn(v[6], v[7]);
    return make_uint4(*(unsigned*)&h0, *(unsigned*)&h1, *(unsigned*)&h2, *(unsigned*)&h3);
}

// ---------------- setup ----------------
__global__ void k_count(const int* __restrict__ dst) {
    int e = blockIdx.x * blockDim.x + threadIdx.x;
    if (e < NE) atomicAdd(&g_cursor[dst[e]], 1);
}

__device__ __forceinline__ int blockscan256(int v, int* warpsums) {
    int lane = threadIdx.x & 31, wid = threadIdx.x >> 5;
    int x = v;
    #pragma unroll
    for (int o = 1; o < 32; o <<= 1) {
        int t = __shfl_up_sync(0xffffffffu, x, o);
        if (lane >= o) x += t;
    }
    if (lane == 31) warpsums[wid] = x;
    __syncthreads();
    if (wid == 0 && lane < 8) {
        int w = warpsums[lane];
        #pragma unroll
        for (int o = 1; o < 8; o <<= 1) {
            int t = __shfl_up_sync(0xffu, w, o);
            if (lane >= o) w += t;
        }
        warpsums[lane] = w;
    }
    __syncthreads();
    return x + (wid > 0 ? warpsums[wid - 1] : 0);
}

__global__ void k_scanA() {
    PDL_SYNC();
    __shared__ int ws[8];
    int i = blockIdx.x * 256 + threadIdx.x;
    int v = (i < NN) ? g_cursor[i] : 0;
    int incl = blockscan256(v, ws);
    if (i < NN) {
        g_rowptr[i] = incl - v;
        g_cursor[i] = incl - v;
    }
    if (threadIdx.x == 255) g_bsum[blockIdx.x] = incl;
}

__global__ void k_scanB() {
    PDL_SYNC();
    __shared__ int ws[8];
    int t = threadIdx.x;
    int v = (t < SCAN_NB) ? g_bsum[t] : 0;
    int incl = blockscan256(v, ws);
    if (t < SCAN_NB) g_boff[t] = incl - v;
    if (t == 255) g_rowptr[NN] = incl;
}

__global__ void k_fill(const int* __restrict__ src, const int* __restrict__ dst) {
    PDL_SYNC();
    int e = blockIdx.x * blockDim.x + threadIdx.x;
    if (e < NE) {
        int d = dst[e];
        int pos = atomicAdd(&g_cursor[d], 1) + g_boff[d >> 8];
        g_cs[pos] = make_int4(src[e], e, d, 0);
    }
}

// ---------------- all-layers edge MLP: writes (src, ew) pairs + degree atomics ----------------
__global__ void __launch_bounds__(256) k_mlp(
    const float* __restrict__ ea,
    const float* __restrict__ m1W1, const float* __restrict__ m1b1,
    const float* __restrict__ m2W1, const float* __restrict__ m2b1,
    const float* __restrict__ hm1W, const float* __restrict__ hm1b,
    const float* __restrict__ hm2W, const float* __restrict__ hm2b)
{
    __shared__ float sW1[NL][FE][FE];
    __shared__ float sb1[NL][FE];
    __shared__ float sW2[NL][FE];
    __shared__ float sb2[NL];
    int tid = threadIdx.x;
    // independent prologue: stage weights (inputs only) while k_fill drains
    for (int t = tid; t < NL * FE * FE; t += blockDim.x) {
        int j = t / (FE * FE), r = t % (FE * FE);
        sW1[j][r / FE][r % FE] = (j == 0) ? m1W1[r] : hm1W[(j - 1) * FE * FE + r];
    }
    for (int t = tid; t < NL * FE; t += blockDim.x) {
        int j = t / FE, r = t % FE;
        sb1[j][r] = (j == 0) ? m1b1[r] : hm1b[(j - 1) * FE + r];
        sW2[j][r] = (j == 0) ? m2W1[r] : hm2W[(j - 1) * FE + r];
    }
    for (int t = tid; t < NL; t += blockDim.x)
        sb2[t] = (t == 0) ? m2b1[0] : hm2b[t - 1];
    PDL_SYNC();
    __syncthreads();

    int p = blockIdx.x * blockDim.x + tid;
    if (p >= NE) return;
    int4 cs = g_cs[p];
    int srcn = cs.x, e = cs.y, dstn = cs.z;
    const float4* row = (const float4*)(ea + (size_t)e * FE);
    float4 v0 = row[0], v1 = row[1], v2 = row[2], v3 = row[3];
    ull ap[FE];
    ap[0]=pk2(v0.x,v0.x); ap[1]=pk2(v0.y,v0.y); ap[2]=pk2(v0.z,v0.z); ap[3]=pk2(v0.w,v0.w);
    ap[4]=pk2(v1.x,v1.x); ap[5]=pk2(v1.y,v1.y); ap[6]=pk2(v1.z,v1.z); ap[7]=pk2(v1.w,v1.w);
    ap[8]=pk2(v2.x,v2.x); ap[9]=pk2(v2.y,v2.y); ap[10]=pk2(v2.z,v2.z); ap[11]=pk2(v2.w,v2.w);
    ap[12]=pk2(v3.x,v3.x); ap[13]=pk2(v3.y,v3.y); ap[14]=pk2(v3.z,v3.z); ap[15]=pk2(v3.w,v3.w);

    #pragma unroll 1
    for (int j = 0; j < NL; j++) {
        ull h[8];
        #pragma unroll
        for (int i = 0; i < 8; i++) h[i] = pk2(sb1[j][2 * i], sb1[j][2 * i + 1]);
        #pragma unroll
        for (int k = 0; k < FE; k++) {
            ulonglong2 w01 = *(const ulonglong2*)&sW1[j][k][0];
            ulonglong2 w23 = *(const ulonglong2*)&sW1[j][k][4];
            ulonglong2 w45 = *(const ulonglong2*)&sW1[j][k][8];
            ulonglong2 w67 = *(const ulonglong2*)&sW1[j][k][12];
            fma2(h[0], ap[k], w01.x); fma2(h[1], ap[k], w01.y);
            fma2(h[2], ap[k], w23.x); fma2(h[3], ap[k], w23.y);
            fma2(h[4], ap[k], w45.x); fma2(h[5], ap[k], w45.y);
            fma2(h[6], ap[k], w67.x); fma2(h[7], ap[k], w67.y);
        }
        float out = sb2[j];
        #pragma unroll
        for (int i = 0; i < 8; i++) {
            float2 hv = upk(h[i]);
            out += fmaxf(hv.x, 0.0f) * sW2[j][2 * i];
            out += fmaxf(hv.y, 0.0f) * sW2[j][2 * i + 1];
        }
        float ew = 1.0f / (1.0f + __expf(-out));
        g_se[(size_t)j * NE + p] = make_int2(srcn, __float_as_int(ew));
        atomicAdd(&g_degacc[(size_t)j * NN + dstn], ew);
    }
}

// dis = rsqrt(1 + degacc)
__global__ void k_dis() {
    PDL_SYNC();
    int t = blockIdx.x * blockDim.x + threadIdx.x;
    if (t < NL * NN) g_dis[t] = rsqrtf(1.0f + g_degacc[t]);
}

// ---------------- per-layer: GEMM (64-row tile, f32x2 math; fp16 in for BN path, fp16 out) ----------------
#define ASTRIDE 68
template <bool BN>
__global__ void __launch_bounds__(128) k_gemm(const float* __restrict__ Xin,
                                              const float* __restrict__ W, int j)
{
    __shared__ float As[64 * ASTRIDE];
    __shared__ float Ws[64 * 64];
    __shared__ float sdis[64];
    __shared__ float smu[CH], sinv[CH];
    int tid = threadIdx.x;
    int row0 = blockIdx.x * 64;
    // independent prologue: weight tile (kernel input) overlaps predecessor tail
    for (int t = tid; t < 4096; t += 128) Ws[t] = W[t];
    PDL_SYNC();
    if (BN) {
        if (tid < CH) {
            double s1 = 0.0, s2 = 0.0;
            #pragma unroll
            for (int s = 0; s < NSLOT; s++) {
                s1 += g_stats2[j][s][0][tid];
                s2 += g_stats2[j][s][1][tid];
            }
            double mu = s1 / (double)NN;
            double var = s2 / (double)NN - mu * mu;
            smu[tid] = (float)mu;
            sinv[tid] = rsqrtf((float)var + 1e-5f);
        }
        __syncthreads();
    }
    if (tid < 64) {
        int gr = row0 + tid;
        sdis[tid] = (gr < NN) ? g_dis[(size_t)j * NN + gr] : 0.0f;
    }
    for (int t = tid; t < 4096; t += 128) {
        int r = t >> 6, c = t & 63;
        int gr = row0 + r;
        float v;
        if (BN) {
            v = (gr < NN) ? __half2float(g_curh[(size_t)gr * CH + c]) : 0.0f;
            v = fmaxf((v - smu[c]) * sinv[c], 0.0f);
        } else {
            v = (gr < NN) ? Xin[(size_t)gr * CH + c] : 0.0f;
        }
        As[c * ASTRIDE + r] = v;
    }
    __syncthreads();

    int ci = tid & 15, ri = tid >> 4;
    const float* Asr = As + ri * 8;
    const float* Wsc = Ws + ci * 4;
    ull acc[4][4];
    #pragma unroll
    for (int a = 0; a < 4; a++)
        #pragma unroll
        for (int b = 0; b < 4; b++) acc[a][b] = 0ull;

    #pragma unroll 8
    for (int k = 0; k < 64; k++) {
        ulonglong2 a01 = *(const ulonglong2*)(Asr + k * ASTRIDE);
        ulonglong2 a23 = *(const ulonglong2*)(Asr + k * ASTRIDE + 4);
        float4 b = *(const float4*)(Wsc + (size_t)k * 64);
        ull b0 = pk2(b.x, b.x), b1 = pk2(b.y, b.y);
        ull b2 = pk2(b.z, b.z), b3 = pk2(b.w, b.w);
        fma2(acc[0][0], a01.x, b0); fma2(acc[0][1], a01.x, b1);
        fma2(acc[0][2], a01.x, b2); fma2(acc[0][3], a01.x, b3);
        fma2(acc[1][0], a01.y, b0); fma2(acc[1][1], a01.y, b1);
        fma2(acc[1][2], a01.y, b2); fma2(acc[1][3], a01.y, b3);
        fma2(acc[2][0], a23.x, b0); fma2(acc[2][1], a23.x, b1);
        fma2(acc[2][2], a23.x, b2); fma2(acc[2][3], a23.x, b3);
        fma2(acc[3][0], a23.y, b0); fma2(acc[3][1], a23.y, b1);
        fma2(acc[3][2], a23.y, b2); fma2(acc[3][3], a23.y, b3);
    }

    #pragma unroll
    for (int p = 0; p < 4; p++) {
        float2 c0 = upk(acc[p][0]), c1 = upk(acc[p][1]);
        float2 c2 = upk(acc[p][2]), c3 = upk(acc[p][3]);
        int r0 = ri * 8 + 2 * p, r1 = r0 + 1;
        int gr0 = row0 + r0, gr1 = row0 + r1;
        if (gr0 < NN) {
            float d = sdis[r0];
            __half2 h01 = __floats2half2_rn(c0.x * d, c1.x * d);
            __half2 h23 = __floats2half2_rn(c2.x * d, c3.x * d);
            *(uint2*)&g_gbuf[(size_t)gr0 * CH + ci * 4] =
                make_uint2(*(unsigned*)&h01, *(unsigned*)&h23);
        }
        if (gr1 < NN) {
            float d = sdis[r1];
            __half2 h01 = __floats2half2_rn(c0.y * d, c1.y * d);
            __half2 h23 = __floats2half2_rn(c2.y * d, c3.y * d);
            *(uint2*)&g_gbuf[(size_t)gr1 * CH + ci * 4] =
                make_uint2(*(unsigned*)&h01, *(unsigned*)&h23);
        }
    }
}

// ---------------- per-layer: aggregation (+fused next-layer BN stats) ----------------
__global__ void __launch_bounds__(256) k_agg(const float* __restrict__ bias,
                                             int j, int mode, int statj)
{
    __shared__ float sst[2][8][CH];
    int wid = threadIdx.x >> 5;
    int gw = blockIdx.x * 8 + wid;
    int lane = threadIdx.x & 31;
    int node = gw;
    bool valid = (node < NN);
    int p0 = 0, p1 = 0;
    if (valid) { p0 = rp(node); p1 = rp(node + 1); }   // rowptr: upstream-complete, pre-sync OK
    PDL_SYNC();
    int eo = lane >> 3, cg = lane & 7;
    const int2* __restrict__ sej = g_se + (size_t)j * NE;
    float acc[8];
    #pragma unroll
    for (int i = 0; i < 8; i++) acc[i] = 0.0f;
    int p = p0 + eo;
    for (; p + 12 < p1; p += 16) {
        int2 e0 = sej[p], e1 = sej[p + 4], e2 = sej[p + 8], e3 = sej[p + 12];
        uint4 q0 = *(const uint4*)(g_gbuf + (size_t)e0.x * CH + cg * 8);
        uint4 q1 = *(const uint4*)(g_gbuf + (size_t)e1.x * CH + cg * 8);
        uint4 q2 = *(const uint4*)(g_gbuf + (size_t)e2.x * CH + cg * 8);
        uint4 q3 = *(const uint4*)(g_gbuf + (size_t)e3.x * CH + cg * 8);
        acc8(acc, __int_as_float(e0.y), q0);
        acc8(acc, __int_as_float(e1.y), q1);
        acc8(acc, __int_as_float(e2.y), q2);
        acc8(acc, __int_as_float(e3.y), q3);
    }
    for (; p + 4 < p1; p += 8) {
        int2 e0 = sej[p], e1 = sej[p + 4];
        uint4 q0 = *(const uint4*)(g_gbuf + (size_t)e0.x * CH + cg * 8);
        uint4 q1 = *(const uint4*)(g_gbuf + (size_t)e1.x * CH + cg * 8);
        acc8(acc, __int_as_float(e0.y), q0);
        acc8(acc, __int_as_float(e1.y), q1);
    }
    if (p < p1) {
        int2 e = sej[p];
        uint4 q = *(const uint4*)(g_gbuf + (size_t)e.x * CH + cg * 8);
        acc8(acc, __int_as_float(e.y), q);
    }
    #pragma unroll
    for (int i = 0; i < 8; i++) {
        acc[i] += __shfl_xor_sync(0xffffffffu, acc[i], 8);
        acc[i] += __shfl_xor_sync(0xffffffffu, acc[i], 16);
    }
    float n[8];
    bool writer = valid && (eo == 0);
    if (writer) {
        float bres[8];
        *(float4*)&bres[0] = *(const float4*)&bias[cg * 8];
        *(float4*)&bres[4] = *(const float4*)&bias[cg * 8 + 4];
        size_t off = (size_t)node * CH + cg * 8;
        uint4 qs = *(const uint4*)(g_gbuf + off);
        float sf[8];
        {
            float2 f0 = __half22float2(*(__half2*)&qs.x);
            float2 f1 = __half22float2(*(__half2*)&qs.y);
            float2 f2 = __half22float2(*(__half2*)&qs.z);
            float2 f3 = __half22float2(*(__half2*)&qs.w);
            sf[0]=f0.x; sf[1]=f0.y; sf[2]=f1.x; sf[3]=f1.y;
            sf[4]=f2.x; sf[5]=f2.y; sf[6]=f3.x; sf[7]=f3.y;
        }
        float dd = g_dis[(size_t)j * NN + node];
        float v[8];
        #pragma unroll
        for (int i = 0; i < 8; i++)
            v[i] = (acc[i] + sf[i]) * dd + bres[i];
        if (mode == 2) {
            float4 s0 = *(const float4*)&g_S[off];
            float4 s1 = *(const float4*)&g_S[off + 4];
            n[0] = v[0] + s0.x; n[1] = v[1] + s0.y; n[2] = v[2] + s0.z; n[3] = v[3] + s0.w;
            n[4] = v[4] + s1.x; n[5] = v[5] + s1.y; n[6] = v[6] + s1.z; n[7] = v[7] + s1.w;
            *(float4*)&g_S[off]     = make_float4(s0.x + n[0], s0.y + n[1], s0.z + n[2], s0.w + n[3]);
            *(float4*)&g_S[off + 4] = make_float4(s1.x + n[4], s1.y + n[5], s1.z + n[6], s1.w + n[7]);
        } else {
            #pragma unroll
            for (int i = 0; i < 8; i++) n[i] = v[i];
            if (mode == 1) {
                *(float4*)&g_S[off]     = make_float4(n[0], n[1], n[2], n[3]);
                *(float4*)&g_S[off + 4] = make_float4(n[4], n[5], n[6], n[7]);
            }
        }
        *(uint4*)&g_curh[off] = pack8h(n);
    }
    if (statj >= 0) {
        #pragma unroll
        for (int i = 0; i < 8; i++) {
            float val = writer ? n[i] : 0.0f;
            if (eo == 0) {
                sst[0][wid][cg * 8 + i] = val;
                sst[1][wid][cg * 8 + i] = val * val;
            }
        }
        __syncthreads();
        int tid = threadIdx.x;
        if (tid < CH) {
            float s1 = 0.0f, s2 = 0.0f;
            #pragma unroll
            for (int w = 0; w < 8; w++) { s1 += sst[0][w][tid]; s2 += sst[1][w][tid]; }
            int slot = blockIdx.x & (NSLOT - 1);
            atomicAdd(&g_stats2[statj][slot][0][tid], (double)s1);
            atomicAdd(&g_stats2[statj][slot][1][tid], (double)s2);
        }
    }
}

// ---------------- readout ----------------
__global__ void k_pool(const int* __restrict__ batch) {
    PDL_SYNC();
    int t = blockIdx.x * blockDim.x + threadIdx.x;
    if (t >= NCHUNK * CH) return;
    int chunk = t >> 6, c = t & 63;
    int n0 = chunk * 16, n1 = min(n0 + 16, NN);
    int curb = batch[n0];
    float m = -1.0f;
    for (int nidx = n0; nidx < n1; nidx++) {
        int b = batch[nidx];
        if (b != curb) {
            atomicMax((int*)&g_pool[curb * CH + c], __float_as_int(fmaxf(m, 0.0f)));
            curb = b;
            m = -1.0f;
        }
        m = fmaxf(m, __half2float(g_curh[(size_t)nidx * CH + c]));
    }
    atomicMax((int*)&g_pool[curb * CH + c], __float_as_int(fmaxf(m, 0.0f)));
}

__global__ void k_final(const float* __restrict__ linW, const float* __restrict__ linb,
                        float* __restrict__ out)
{
    PDL_SYNC();
    int g = blockIdx.x, c = threadIdx.x;
    float p = g_pool[g * CH + c];
    float v0 = p * linW[c * 2 + 0];
    float v1 = p * linW[c * 2 + 1];
    #pragma unroll
    for (int o = 16; o; o >>= 1) {
        v0 += __shfl_down_sync(0xffffffffu, v0, o);
        v1 += __shfl_down_sync(0xffffffffu, v1, o);
    }
    __shared__ float s0[2], s1[2];
    if ((c & 31) == 0) { s0[c >> 5] = v0; s1[c >> 5] = v1; }
    __syncthreads();
    if (c == 0) {
        out[g * 2 + 0] = s0[0] + s0[1] + linb[0];
        out[g * 2 + 1] = s1[0] + s1[1] + linb[1];
    }
}

// ---------------- host ----------------
extern "C" void kernel_launch(void* const* d_in, const int* in_sizes, int n_in,
                              void* d_out, int out_size)
{
    const float* x     = (const float*)d_in[0];
    const int*   ei    = (const int*)d_in[1];
    const int*   srcp  = ei;
    const int*   dstp  = ei + NE;
    const int*   batch = (const int*)d_in[2];
    int base = (in_sizes[3] == 1) ? 4 : 3;
    const float* edge_attr = (const float*)d_in[base + 0];
    const float* Wlin1 = (const float*)d_in[base + 1];
    const float* bias1 = (const float*)d_in[base + 2];
    const float* m1W1  = (const float*)d_in[base + 3];
    const float* m1b1  = (const float*)d_in[base + 4];
    const float* m2W1  = (const float*)d_in[base + 5];
    const float* m2b1  = (const float*)d_in[base + 6];
    const float* hWlin = (const float*)d_in[base + 7];
    const float* hbias = (const float*)d_in[base + 8];
    const float* hm1W  = (const float*)d_in[base + 9];
    const float* hm1b  = (const float*)d_in[base + 10];
    const float* hm2W  = (const float*)d_in[base + 11];
    const float* hm2b  = (const float*)d_in[base + 12];
    const float* linW  = (const float*)d_in[base + 13];
    const float* linb  = (const float*)d_in[base + 14];

    void* p_cursor = nullptr;
    void* p_stats  = nullptr;
    void* p_pool   = nullptr;
    void* p_deg    = nullptr;
    cudaGetSymbolAddress(&p_cursor, g_cursor);
    cudaGetSymbolAddress(&p_stats,  g_stats2);
    cudaGetSymbolAddress(&p_pool,   g_pool);
    cudaGetSymbolAddress(&p_deg,    g_degacc);
    cudaMemsetAsync(p_cursor, 0, sizeof(int) * NN);
    cudaMemsetAsync(p_stats,  0, sizeof(double) * NL * NSLOT * 2 * CH);
    cudaMemsetAsync(p_pool,   0, sizeof(float) * NG * CH);
    cudaMemsetAsync(p_deg,    0, sizeof(float) * NL * NN);

    cudaLaunchAttribute pdlAttr;
    pdlAttr.id = cudaLaunchAttributeProgrammaticStreamSerialization;
    pdlAttr.val.programmaticStreamSerializationAllowed = 1;
    cudaLaunchConfig_t cfg = {};
    cfg.stream = 0;
    cfg.attrs = &pdlAttr;
    cfg.numAttrs = 1;

    // k_count: normal launch (predecessor is a memset node)
    k_count<<<(NE + 255) / 256, 256>>>(dstp);

    cfg.gridDim = dim3(SCAN_NB); cfg.blockDim = dim3(256);
    cudaLaunchKernelEx(&cfg, k_scanA);
    cfg.gridDim = dim3(1); cfg.blockDim = dim3(256);
    cudaLaunchKernelEx(&cfg, k_scanB);
    cfg.gridDim = dim3((NE + 255) / 256); cfg.blockDim = dim3(256);
    cudaLaunchKernelEx(&cfg, k_fill, srcp, dstp);
    cfg.gridDim = dim3((NE + 255) / 256); cfg.blockDim = dim3(256);
    cudaLaunchKernelEx(&cfg, k_mlp, edge_attr, m1W1, m1b1, m2W1, m2b1,
                       hm1W, hm1b, hm2W, hm2b);
    cfg.gridDim = dim3((NL * NN + 255) / 256); cfg.blockDim = dim3(256);
    cudaLaunchKernelEx(&cfg, k_dis);

    for (int j = 0; j < NL; j++) {
        cfg.gridDim = dim3((NN + 63) / 64); cfg.blockDim = dim3(128);
        if (j == 0) {
            cudaLaunchKernelEx(&cfg, k_gemm<false>, x, Wlin1, 0);
        } else {
            cudaLaunchKernelEx(&cfg, k_gemm<true>,
                               x, (const float*)(hWlin + (size_t)(j - 1) * CH * CH), j);
        }
        int mode = (j == 0) ? 1 : ((j % 2 == 0) ? 2 : 0);
        int statj = (j < NL - 1) ? (j + 1) : -1;
        const float* bias = (j == 0) ? bias1 : hbias + (size_t)(j - 1) * CH;
        cfg.gridDim = dim3((NN + 7) / 8); cfg.blockDim = dim3(256);
        cudaLaunchKernelEx(&cfg, k_agg, bias, j, mode, statj);
    }

    cfg.gridDim = dim3((NCHUNK * CH + 255) / 256); cfg.blockDim = dim3(256);
    cudaLaunchKernelEx(&cfg, k_pool, batch);
    cfg.gridDim = dim3(NG); cfg.blockDim = dim3(64);
    cudaLaunchKernelEx(&cfg, k_final, linW, linb, (float*)d_out);
    (void)n_in; (void)out_size;
}